// round 4
// baseline (speedup 1.0000x reference)
#include <cuda_runtime.h>
#include <cstdint>

#define Bb 32
#define Ss 256
#define Ll 64
#define Dd 100
#define Mm 20
#define NSLOT (Bb * Mm)   // 640
#define NBLK 444          // 3 blocks per SM, single wave, 1-2 slots per block

// ---------------- scratch (no allocations allowed) ----------------
__device__ __align__(16) float g_enc[Bb * Ss * Dd];   // [B,S,D]
__device__ __align__(16) float g_sW [Bb * Ss * Dd];   // [B,S,D] enc @ W^T
__device__ __align__(16) float g_kg [Bb * Ss * Mm];   // [B,S,M] enc . keys[m]

// ---------------- helpers ----------------
__device__ __forceinline__ void fma2(unsigned long long& acc,
                                     unsigned long long a,
                                     unsigned long long b) {
    asm("fma.rn.f32x2 %0, %1, %2, %0;" : "+l"(acc) : "l"(a), "l"(b));
}
__device__ __forceinline__ unsigned long long pack2(float lo, float hi) {
    unsigned long long r;
    asm("mov.b64 %0, {%1, %2};" : "=l"(r) : "f"(lo), "f"(hi));
    return r;
}
__device__ __forceinline__ float sum2(unsigned long long v) {
    float lo, hi;
    asm("mov.b64 {%0, %1}, %2;" : "=f"(lo), "=f"(hi) : "l"(v));
    return lo + hi;
}
// paired warp reduction: two independent 5-deep shuffle chains, interleaved
__device__ __forceinline__ void warp_red2(float& a, float& b) {
#pragma unroll
    for (int o = 16; o > 0; o >>= 1) {
        a += __shfl_down_sync(0xffffffffu, a, o);
        b += __shfl_down_sync(0xffffffffu, b, o);
    }
}

// ================= K1: encode (float4 path) =================
// enc[b,s,:] = sum_l batch[b,s,l,:] * mult[l,:]
__global__ void k_encode(const float4* __restrict__ batch4,
                         const float4* __restrict__ mult4,
                         float4* __restrict__ enc4) {
    __shared__ float4 sm4[100];
    int row = blockIdx.x;           // b*S + s
    int t = threadIdx.x;

    if (t < 100) {
        int c  = t % 25;            // float4 column (dims 4c..4c+3)
        int lg = t / 25;            // l residue class
        const float4* bp = batch4 + (size_t)row * (Ll * 25);
        float4 acc = make_float4(0.f, 0.f, 0.f, 0.f);
#pragma unroll
        for (int k = 0; k < 16; ++k) {
            int l = lg + 4 * k;
            float4 bv = bp[l * 25 + c];
            float4 mv = __ldg(&mult4[l * 25 + c]);
            acc.x += bv.x * mv.x;
            acc.y += bv.y * mv.y;
            acc.z += bv.z * mv.z;
            acc.w += bv.w * mv.w;
        }
        sm4[t] = acc;
    }
    __syncthreads();
    if (t < 25) {
        float4 a = sm4[t], b = sm4[t + 25], c = sm4[t + 50], d = sm4[t + 75];
        float4 r;
        r.x = (a.x + b.x) + (c.x + d.x);
        r.y = (a.y + b.y) + (c.y + d.y);
        r.z = (a.z + b.z) + (c.z + d.z);
        r.w = (a.w + b.w) + (c.w + d.w);
        enc4[(size_t)row * 25 + t] = r;
    }
}

// ================= K2: project sW = enc @ W^T, kg = enc @ keys^T =================
#define R2 16
__global__ void k_project(const float* __restrict__ W,
                          const float* __restrict__ keys) {
    __shared__ float Wt[Dd * Dd];        // Wt[d*Dd + e] = W[e*Dd + d]
    __shared__ float encs[R2][Dd];
    int t = threadIdx.x;
    int row0 = blockIdx.x * R2;

    for (int idx = t; idx < Dd * Dd; idx += blockDim.x) {
        int e = idx / Dd, d = idx % Dd;
        Wt[d * Dd + e] = W[idx];
    }
    for (int idx = t; idx < R2 * Dd; idx += blockDim.x)
        ((float*)encs)[idx] = g_enc[(size_t)row0 * Dd + idx];
    __syncthreads();

    if (t < Dd) {
        for (int r = 0; r < R2; ++r) {
            float acc = 0.f;
#pragma unroll 4
            for (int d = 0; d < Dd; ++d)
                acc += encs[r][d] * Wt[d * Dd + t];
            g_sW[(size_t)(row0 + r) * Dd + t] = acc;
        }
    } else if (t < Dd + Mm) {
        int m = t - Dd;
        for (int r = 0; r < R2; ++r) {
            float acc = 0.f;
#pragma unroll 4
            for (int d = 0; d < Dd; ++d)
                acc += encs[r][d] * __ldg(&keys[m * Dd + d]);
            g_kg[(size_t)(row0 + r) * Mm + m] = acc;
        }
    }
}

// ================= K3: scan; 444 blocks, 1-2 slots each =================
__global__ void __launch_bounds__(128, 3)
k_scan(const float* __restrict__ keys, const float* __restrict__ U,
       const float* __restrict__ V, const float* __restrict__ prelu_a,
       float* __restrict__ out) {
    __shared__ __align__(16) float h0s[128];
    __shared__ __align__(16) float h1s[128];
    __shared__ float2 redA[4];
    __shared__ float2 redB[4];

    int bid = blockIdx.x;
    int sl0 = (bid * NSLOT) / NBLK;
    int sle = ((bid + 1) * NSLOT) / NBLK;
    bool two = (sle - sl0) == 2;
    int sl1 = two ? sl0 + 1 : sl0;
    int b0 = sl0 / Mm, m0 = sl0 % Mm;
    int b1 = sl1 / Mm, m1 = sl1 % Mm;

    int e = threadIdx.x;
    int lane = e & 31, wid = e >> 5;
    float aprelu = __ldg(prelu_a);

    // U row of this output dim: 50 b64 f32x2 registers
    unsigned long long U2[50];
    if (e < Dd) {
        const float2* up = (const float2*)(U + e * Dd);
#pragma unroll
        for (int i = 0; i < 50; ++i) {
            float2 u = __ldg(up + i);
            U2[i] = pack2(u.x, u.y);
        }
    } else {
#pragma unroll
        for (int i = 0; i < 50; ++i) U2[i] = 0ull;
    }

    // step-invariant keysV[m,e]; initial memory = keys (r starts at 1)
    float kv0 = 0.f, kv1 = 0.f, hold0 = 0.f, hold1 = 0.f;
    if (e < Dd) {
#pragma unroll 4
        for (int d = 0; d < Dd; ++d) {
            float ve = __ldg(&V[e * Dd + d]);
            kv0 += __ldg(&keys[m0 * Dd + d]) * ve;
            kv1 += __ldg(&keys[m1 * Dd + d]) * ve;
        }
        hold0 = __ldg(&keys[m0 * Dd + e]);
        hold1 = __ldg(&keys[m1 * Dd + e]);
        h0s[e] = hold0;
        h1s[e] = hold1;
    } else {
        h0s[e] = 0.f;
        h1s[e] = 0.f;
    }

    const float* encp0 = g_enc + (size_t)b0 * Ss * Dd;
    const float* swp0  = g_sW  + (size_t)b0 * Ss * Dd;
    const float* kgp0  = g_kg  + (size_t)b0 * Ss * Mm + m0;
    const float* encp1 = g_enc + (size_t)b1 * Ss * Dd;
    const float* swp1  = g_sW  + (size_t)b1 * Ss * Dd;
    const float* kgp1  = g_kg  + (size_t)b1 * Ss * Mm + m1;

    float encv0 = (e < Dd) ? encp0[e] : 0.f;
    float swv0  = (e < Dd) ? swp0[e]  : 0.f;
    float kg0   = __ldg(kgp0);
    float encv1 = 0.f, swv1 = 0.f, kg1 = 0.f;
    if (two) {
        encv1 = (e < Dd) ? encp1[e] : 0.f;
        swv1  = (e < Dd) ? swp1[e]  : 0.f;
        kg1   = __ldg(kgp1);
    }
    float r0 = 1.f, r1 = 1.f;   // deferred normalization scalars
    __syncthreads();

    const ulonglong2* h0q = (const ulonglong2*)h0s;
    const ulonglong2* h1q = (const ulonglong2*)h1s;

    for (int s = 0; s < Ss; ++s) {
        // ---- matvec over UN-normalized h; true value = r_j * acc_j ----
        unsigned long long a0 = 0ull, a0b = 0ull, a1 = 0ull, a1b = 0ull;
#pragma unroll
        for (int i = 0; i < 25; ++i) {
            ulonglong2 x = h0q[i];
            fma2(a0,  x.x, U2[2 * i]);
            fma2(a0b, x.y, U2[2 * i + 1]);
            if (two) {
                ulonglong2 y = h1q[i];
                fma2(a1,  y.x, U2[2 * i]);
                fma2(a1b, y.y, U2[2 * i + 1]);
            }
        }

        // ---- memory-gate dots (normalized hold in registers) ----
        float wp0 = hold0 * encv0;
        float wp1 = two ? hold1 * encv1 : 0.f;
        warp_red2(wp0, wp1);
        if (lane == 0) redA[wid] = make_float2(wp0, wp1);
        __syncthreads();    // bar1: redA visible; all matvec reads of h done

        float mg0 = redA[0].x + redA[1].x + redA[2].x + redA[3].x;
        float g0 = 1.f / (1.f + __expf(-(mg0 + kg0)));
        float c0 = kv0 + swv0 + r0 * (sum2(a0) + sum2(a0b));
        c0 = (c0 >= 0.f) ? c0 : aprelu * c0;
        float hn0 = hold0 + c0 * g0;
        if (e >= Dd) hn0 = 0.f;
        h0s[e] = hn0;                       // un-normalized; scaled by r0 next step

        float hn1 = 0.f;
        if (two) {
            float mg1 = redA[0].y + redA[1].y + redA[2].y + redA[3].y;
            float g1 = 1.f / (1.f + __expf(-(mg1 + kg1)));
            float c1 = kv1 + swv1 + r1 * (sum2(a1) + sum2(a1b));
            c1 = (c1 >= 0.f) ? c1 : aprelu * c1;
            hn1 = hold1 + c1 * g1;
            if (e >= Dd) hn1 = 0.f;
            h1s[e] = hn1;
        }

        float wq0 = hn0 * hn0;
        float wq1 = two ? hn1 * hn1 : 0.f;
        warp_red2(wq0, wq1);
        if (lane == 0) redB[wid] = make_float2(wq0, wq1);

        // ---- prefetch next step's inputs (cover L2 latency over bar2) ----
        if (s + 1 < Ss) {
            encv0 = (e < Dd) ? encp0[(size_t)(s + 1) * Dd + e] : 0.f;
            swv0  = (e < Dd) ? swp0[(size_t)(s + 1) * Dd + e]  : 0.f;
            kg0   = __ldg(kgp0 + (size_t)(s + 1) * Mm);
            if (two) {
                encv1 = (e < Dd) ? encp1[(size_t)(s + 1) * Dd + e] : 0.f;
                swv1  = (e < Dd) ? swp1[(size_t)(s + 1) * Dd + e]  : 0.f;
                kg1   = __ldg(kgp1 + (size_t)(s + 1) * Mm);
            }
        }
        __syncthreads();    // bar2: h writes + redB visible

        float n0 = redB[0].x + redB[1].x + redB[2].x + redB[3].x;
        r0 = rsqrtf(n0);
        hold0 = hn0 * r0;   // thread-local normalized copy
        if (two) {
            float n1 = redB[0].y + redB[1].y + redB[2].y + redB[3].y;
            r1 = rsqrtf(n1);
            hold1 = hn1 * r1;
        }
    }

    if (e < Dd) {
        out[(size_t)sl0 * Dd + e] = hold0;
        if (two) out[(size_t)sl1 * Dd + e] = hold1;
    }
}

// ================= launcher =================
extern "C" void kernel_launch(void* const* d_in, const int* in_sizes, int n_in,
                              void* d_out, int out_size) {
    const float* batch = (const float*)d_in[0];  // [B,S,L,D]
    const float* mult  = (const float*)d_in[1];  // [L,D]
    const float* keys  = (const float*)d_in[2];  // [M,D]
    const float* U     = (const float*)d_in[3];  // [D,D]
    const float* V     = (const float*)d_in[4];  // [D,D]
    const float* W     = (const float*)d_in[5];  // [D,D]
    const float* pa    = (const float*)d_in[6];  // scalar
    float* out = (float*)d_out;                  // [B,M,D]

    float4* enc4;
    cudaGetSymbolAddress((void**)&enc4, g_enc);

    k_encode<<<Bb * Ss, 128>>>((const float4*)batch, (const float4*)mult, enc4);
    k_project<<<(Bb * Ss) / R2, 128>>>(W, keys);
    k_scan<<<NBLK, 128>>>(keys, U, V, pa, out);
}

// round 5
// speedup vs baseline: 1.0467x; 1.0467x over previous
#include <cuda_runtime.h>
#include <cstdint>

#define Bb 32
#define Ss 256
#define Ll 64
#define Dd 100
#define Mm 20
#define NSLOT (Bb * Mm)   // 640
#define NBLK (NSLOT / 2)  // 320 blocks, 2 slots each (same batch)

// ---------------- scratch (no allocations allowed) ----------------
__device__ __align__(16) float  g_enc [Bb * Ss * Dd];      // [B,S,D]
__device__ __align__(16) float2 g_esw [Bb * Ss * Dd];      // [B,S,D] (enc, enc@W^T)
__device__ __align__(16) float  g_kg  [Bb * Ss * Mm];      // [B,S,M] enc . keys[m]
__device__ __align__(16) float  g_hold[NSLOT * Dd];        // normalized state between scan parts

// ---------------- helpers ----------------
__device__ __forceinline__ void fma2(unsigned long long& acc,
                                     unsigned long long a,
                                     unsigned long long b) {
    asm("fma.rn.f32x2 %0, %1, %2, %0;" : "+l"(acc) : "l"(a), "l"(b));
}
__device__ __forceinline__ unsigned long long pack2(float lo, float hi) {
    unsigned long long r;
    asm("mov.b64 %0, {%1, %2};" : "=l"(r) : "f"(lo), "f"(hi));
    return r;
}
__device__ __forceinline__ float sum2(unsigned long long v) {
    float lo, hi;
    asm("mov.b64 {%0, %1}, %2;" : "=f"(lo), "=f"(hi) : "l"(v));
    return lo + hi;
}

// ================= K1: encode (float4 path) =================
__global__ void k_encode(const float4* __restrict__ batch4,
                         const float4* __restrict__ mult4,
                         float4* __restrict__ enc4) {
    __shared__ float4 sm4[100];
    int row = blockIdx.x;           // b*S + s
    int t = threadIdx.x;

    if (t < 100) {
        int c  = t % 25;
        int lg = t / 25;
        const float4* bp = batch4 + (size_t)row * (Ll * 25);
        float4 acc = make_float4(0.f, 0.f, 0.f, 0.f);
#pragma unroll
        for (int k = 0; k < 16; ++k) {
            int l = lg + 4 * k;
            float4 bv = bp[l * 25 + c];
            float4 mv = __ldg(&mult4[l * 25 + c]);
            acc.x += bv.x * mv.x;
            acc.y += bv.y * mv.y;
            acc.z += bv.z * mv.z;
            acc.w += bv.w * mv.w;
        }
        sm4[t] = acc;
    }
    __syncthreads();
    if (t < 25) {
        float4 a = sm4[t], b = sm4[t + 25], c = sm4[t + 50], d = sm4[t + 75];
        float4 r;
        r.x = (a.x + b.x) + (c.x + d.x);
        r.y = (a.y + b.y) + (c.y + d.y);
        r.z = (a.z + b.z) + (c.z + d.z);
        r.w = (a.w + b.w) + (c.w + d.w);
        enc4[(size_t)row * 25 + t] = r;
    }
}

// ================= K2: project -> g_esw=(enc, enc@W^T), g_kg =================
#define R2 16
__global__ void k_project(const float* __restrict__ W,
                          const float* __restrict__ keys) {
    __shared__ float Wt[Dd * Dd];        // Wt[d*Dd + e] = W[e*Dd + d]
    __shared__ float encs[R2][Dd];
    int t = threadIdx.x;
    int row0 = blockIdx.x * R2;

    for (int idx = t; idx < Dd * Dd; idx += blockDim.x) {
        int e = idx / Dd, d = idx % Dd;
        Wt[d * Dd + e] = W[idx];
    }
    for (int idx = t; idx < R2 * Dd; idx += blockDim.x)
        ((float*)encs)[idx] = g_enc[(size_t)row0 * Dd + idx];
    __syncthreads();

    if (t < Dd) {
        for (int r = 0; r < R2; ++r) {
            float acc = 0.f;
#pragma unroll 4
            for (int d = 0; d < Dd; ++d)
                acc += encs[r][d] * Wt[d * Dd + t];
            g_esw[(size_t)(row0 + r) * Dd + t] = make_float2(encs[r][t], acc);
        }
    } else if (t < Dd + Mm) {
        int m = t - Dd;
        for (int r = 0; r < R2; ++r) {
            float acc = 0.f;
#pragma unroll 4
            for (int d = 0; d < Dd; ++d)
                acc += encs[r][d] * __ldg(&keys[m * Dd + d]);
            g_kg[(size_t)(row0 + r) * Mm + m] = acc;
        }
    }
}

// ================= K3: scan slice [s_begin, s_end) =================
// phase 0: init from keys, save normalized state to g_hold
// phase 1: init from g_hold (r=1, hh=1), write final result to out
__global__ void __launch_bounds__(128, 3)
k_scan(const float* __restrict__ keys, const float* __restrict__ U,
       const float* __restrict__ V, const float* __restrict__ prelu_a,
       float* __restrict__ out, int s_begin, int s_end, int phase) {
    __shared__ __align__(16) float h0s[128];
    __shared__ __align__(16) float h1s[128];
    __shared__ float4 red4[4];   // (wp0, wp1, hc0, hc1) per warp
    __shared__ float2 red2[4];   // (cc0, cc1) per warp

    int bid = blockIdx.x;
    int sl0 = 2 * bid, sl1 = sl0 + 1;
    int b  = sl0 / Mm;
    int m0 = sl0 % Mm, m1 = m0 + 1;   // same batch, Mm even

    int e = threadIdx.x;
    int lane = e & 31, wid = e >> 5;
    float aprelu = __ldg(prelu_a);

    // U row of this output dim: 50 b64 f32x2 registers
    unsigned long long U2[50];
    if (e < Dd) {
        const float2* up = (const float2*)(U + e * Dd);
#pragma unroll
        for (int i = 0; i < 50; ++i) {
            float2 u = __ldg(up + i);
            U2[i] = pack2(u.x, u.y);
        }
    } else {
#pragma unroll
        for (int i = 0; i < 50; ++i) U2[i] = 0ull;
    }

    // step-invariant keysV[m,e]
    float kv0 = 0.f, kv1 = 0.f;
    if (e < Dd) {
#pragma unroll 4
        for (int d = 0; d < Dd; ++d) {
            float ve = __ldg(&V[e * Dd + d]);
            kv0 += __ldg(&keys[m0 * Dd + d]) * ve;
            kv1 += __ldg(&keys[m1 * Dd + d]) * ve;
        }
    }

    // state init
    float hold0 = 0.f, hold1 = 0.f, hh0 = 1.f, hh1 = 1.f;
    float r0 = 1.f, r1 = 1.f;
    if (phase == 0) {
        if (e < Dd) {
            hold0 = __ldg(&keys[m0 * Dd + e]);
            hold1 = __ldg(&keys[m1 * Dd + e]);
        }
        // hh = ||keys_m||^2 (memory starts UN-normalized)
        float q0 = hold0 * hold0, q1 = hold1 * hold1;
#pragma unroll
        for (int o = 16; o > 0; o >>= 1) {
            q0 += __shfl_down_sync(0xffffffffu, q0, o);
            q1 += __shfl_down_sync(0xffffffffu, q1, o);
        }
        if (lane == 0) red2[wid] = make_float2(q0, q1);
        __syncthreads();
        hh0 = red2[0].x + red2[1].x + red2[2].x + red2[3].x;
        hh1 = red2[0].y + red2[1].y + red2[2].y + red2[3].y;
        __syncthreads();
    } else {
        if (e < Dd) {
            hold0 = g_hold[(size_t)sl0 * Dd + e];   // normalized: r=1, hh=1
            hold1 = g_hold[(size_t)sl1 * Dd + e];
        }
    }
    h0s[e] = (e < Dd) ? hold0 : 0.f;
    h1s[e] = (e < Dd) ? hold1 : 0.f;

    const float2* eswp = g_esw + (size_t)b * Ss * Dd;
    const float2* kgp  = (const float2*)(g_kg + (size_t)b * Ss * Mm + m0);  // m0 even -> 8B aligned

    float2 esw = (e < Dd) ? eswp[(size_t)s_begin * Dd + e] : make_float2(0.f, 0.f);
    float2 kg  = __ldg(&kgp[(size_t)s_begin * (Mm / 2)]);
    __syncthreads();

    const ulonglong2* h0q = (const ulonglong2*)h0s;
    const ulonglong2* h1q = (const ulonglong2*)h1s;

    for (int s = s_begin; s < s_end; ++s) {
        // ---- matvec over UN-normalized h (true value = r_j * acc) ----
        unsigned long long a0 = 0ull, a0b = 0ull, a1 = 0ull, a1b = 0ull;
#pragma unroll
        for (int i = 0; i < 25; ++i) {
            ulonglong2 x = h0q[i];
            ulonglong2 y = h1q[i];
            fma2(a0,  x.x, U2[2 * i]);
            fma2(a0b, x.y, U2[2 * i + 1]);
            fma2(a1,  y.x, U2[2 * i]);
            fma2(a1b, y.y, U2[2 * i + 1]);
        }

        // ---- candidates (pre-gate) ----
        float c0 = kv0 + esw.y + r0 * (sum2(a0) + sum2(a0b));
        float c1 = kv1 + esw.y + r1 * (sum2(a1) + sum2(a1b));
        c0 = (c0 >= 0.f) ? c0 : aprelu * c0;
        c1 = (c1 >= 0.f) ? c1 : aprelu * c1;

        // ---- single merged reduction: wp (hold.enc), hc (hold.c), cc (c.c) ----
        float wp0 = hold0 * esw.x, wp1 = hold1 * esw.x;
        float hc0 = hold0 * c0,    hc1 = hold1 * c1;
        float cc0 = c0 * c0,       cc1 = c1 * c1;
#pragma unroll
        for (int o = 16; o > 0; o >>= 1) {
            wp0 += __shfl_down_sync(0xffffffffu, wp0, o);
            wp1 += __shfl_down_sync(0xffffffffu, wp1, o);
            hc0 += __shfl_down_sync(0xffffffffu, hc0, o);
            hc1 += __shfl_down_sync(0xffffffffu, hc1, o);
            cc0 += __shfl_down_sync(0xffffffffu, cc0, o);
            cc1 += __shfl_down_sync(0xffffffffu, cc1, o);
        }
        if (lane == 0) {
            red4[wid] = make_float4(wp0, wp1, hc0, hc1);
            red2[wid] = make_float2(cc0, cc1);
        }

        // ---- prefetch next step (covers latency across both barriers) ----
        float2 eswn = make_float2(0.f, 0.f), kgn = kg;
        if (s + 1 < s_end) {
            eswn = (e < Dd) ? eswp[(size_t)(s + 1) * Dd + e] : make_float2(0.f, 0.f);
            kgn  = __ldg(&kgp[(size_t)(s + 1) * (Mm / 2)]);
        }
        __syncthreads();   // bar1: partials visible; matvec reads of h done

        float4 A = red4[0], B4 = red4[1], C4 = red4[2], D4 = red4[3];
        float2 E = red2[0], F = red2[1], G2 = red2[2], H2 = red2[3];
        float mg0 = (A.x + B4.x) + (C4.x + D4.x);
        float mg1 = (A.y + B4.y) + (C4.y + D4.y);
        float shc0 = (A.z + B4.z) + (C4.z + D4.z);
        float shc1 = (A.w + B4.w) + (C4.w + D4.w);
        float scc0 = (E.x + F.x) + (G2.x + H2.x);
        float scc1 = (E.y + F.y) + (G2.y + H2.y);

        float g0 = 1.f / (1.f + __expf(-(mg0 + kg.x)));
        float g1 = 1.f / (1.f + __expf(-(mg1 + kg.y)));

        // ||hn||^2 = hh + 2 g (hold.c) + g^2 (c.c)   (no second reduction!)
        float n0 = hh0 + 2.f * g0 * shc0 + g0 * g0 * scc0;
        float n1 = hh1 + 2.f * g1 * shc1 + g1 * g1 * scc1;
        r0 = rsqrtf(n0);
        r1 = rsqrtf(n1);

        float hn0 = hold0 + c0 * g0;
        float hn1 = hold1 + c1 * g1;
        if (e >= Dd) { hn0 = 0.f; hn1 = 0.f; }
        h0s[e] = hn0;                        // un-normalized; scaled by r next step
        h1s[e] = hn1;
        __syncthreads();   // bar2: h visible for next matvec

        hold0 = hn0 * r0;  // normalized register copy (off critical path)
        hold1 = hn1 * r1;
        hh0 = 1.f;
        hh1 = 1.f;
        esw = eswn;
        kg = kgn;
    }

    if (e < Dd) {
        if (phase == 0) {
            g_hold[(size_t)sl0 * Dd + e] = hold0;   // normalized -> part 2 uses r=1, hh=1
            g_hold[(size_t)sl1 * Dd + e] = hold1;
        } else {
            out[(size_t)sl0 * Dd + e] = hold0;
            out[(size_t)sl1 * Dd + e] = hold1;
        }
    }
}

// ================= launcher =================
extern "C" void kernel_launch(void* const* d_in, const int* in_sizes, int n_in,
                              void* d_out, int out_size) {
    const float* batch = (const float*)d_in[0];  // [B,S,L,D]
    const float* mult  = (const float*)d_in[1];  // [L,D]
    const float* keys  = (const float*)d_in[2];  // [M,D]
    const float* U     = (const float*)d_in[3];  // [D,D]
    const float* V     = (const float*)d_in[4];  // [D,D]
    const float* W     = (const float*)d_in[5];  // [D,D]
    const float* pa    = (const float*)d_in[6];  // scalar
    float* out = (float*)d_out;                  // [B,M,D]

    float4* enc4;
    cudaGetSymbolAddress((void**)&enc4, g_enc);

    k_encode<<<Bb * Ss, 128>>>((const float4*)batch, (const float4*)mult, enc4);
    k_project<<<(Bb * Ss) / R2, 128>>>(W, keys);
    k_scan<<<NBLK, 128>>>(keys, U, V, pa, out, 0, Ss / 2, 0);
    k_scan<<<NBLK, 128>>>(keys, U, V, pa, out, Ss / 2, Ss, 1);
}